// round 9
// baseline (speedup 1.0000x reference)
#include <cuda_runtime.h>
#include <cuda_bf16.h>
#include <math.h>
#include <stdint.h>

#define D_MODEL 512
#define D_LOW   64
#define NUM_BINS 39
#define NB_PAD  40
#define DIST_MIN_F 2.0f
#define DIST_MAX_F 22.0f
#define BIN_W  ((DIST_MAX_F - DIST_MIN_F) / (float)(NUM_BINS - 1))
#define LN_EPS 1e-5f
#define MAX_ROWS 4096
#define JT 128

__device__ float g_U[MAX_ROWS * D_LOW];
__device__ unsigned long long g_Vb[MAX_ROWS * (D_LOW / 4)];  // 4 bf16 per u64
__device__ float g_Wt[D_MODEL * 128];
__device__ double g_ce[8];
__device__ unsigned int g_cnt[8];
__device__ unsigned int g_done;

__device__ __forceinline__ uint32_t smem_u32(const void* p) {
    uint32_t a;
    asm("{ .reg .u64 t; cvta.to.shared.u64 t, %1; cvt.u32.u64 %0, t; }" : "=r"(a) : "l"(p));
    return a;
}
#define CVT_BF2(res, lo, hi) \
    asm("cvt.rn.satfinite.bf16x2.f32 %0, %1, %2;" : "=r"(res) : "f"(hi), "f"(lo))
#define MULBF2(res, a, b) \
    asm("mul.bf16x2 %0, %1, %2;" : "=r"(res) : "r"(a), "r"(b))

#define MMA_BF16(d, a0, a1, a2, a3, b0, b1) \
    asm volatile("mma.sync.aligned.m16n8k16.row.col.f32.bf16.bf16.f32 " \
                 "{%0,%1,%2,%3}, {%4,%5,%6,%7}, {%8,%9}, {%0,%1,%2,%3};" \
                 : "+f"((d)[0]), "+f"((d)[1]), "+f"((d)[2]), "+f"((d)[3]) \
                 : "r"(a0), "r"(a1), "r"(a2), "r"(a3), "r"(b0), "r"(b1))

// ---------------------------------------------------------------------------
// Kernel 0: transpose wu/wv into c-major Wt[512][128]; zero accumulators.
// ---------------------------------------------------------------------------
__global__ void __launch_bounds__(256) transpose_kernel(
    const float* __restrict__ wu_w, const float* __restrict__ wv_w)
{
    int idx = blockIdx.x * 256 + threadIdx.x;
    int c = idx >> 7;
    int o = idx & 127;
    float v = (o < D_LOW) ? wu_w[(size_t)o * D_MODEL + c]
                          : wv_w[(size_t)(o - D_LOW) * D_MODEL + c];
    g_Wt[idx] = v;
    if (idx < 8) { g_ce[idx] = 0.0; g_cnt[idx] = 0u; }
    if (idx == 8) g_done = 0u;
}

// ---------------------------------------------------------------------------
// Kernel 1: LayerNorm + projections. U -> fp32, V -> bf16 packed.
// ---------------------------------------------------------------------------
#define TR 16

__global__ void __launch_bounds__(256) prep_kernel(
    const float* __restrict__ h_res,
    const float* __restrict__ ln_w, const float* __restrict__ ln_b,
    const float* __restrict__ wu_b, const float* __restrict__ wv_b)
{
    __shared__ __align__(16) float sh[TR * D_MODEL];

    int t    = threadIdx.x;
    int warp = t >> 5;
    int lane = t & 31;

    #pragma unroll
    for (int rr = 0; rr < 2; rr++) {
        int lr  = warp * 2 + rr;
        size_t row = (size_t)blockIdx.x * TR + lr;
        const float4* hp = reinterpret_cast<const float4*>(h_res) + row * (D_MODEL / 4);
        float4 a[4];
        #pragma unroll
        for (int q = 0; q < 4; q++) a[q] = hp[lane + 32 * q];
        float s = 0.0f, sq = 0.0f;
        #pragma unroll
        for (int q = 0; q < 4; q++) {
            s  += a[q].x + a[q].y + a[q].z + a[q].w;
            sq += a[q].x*a[q].x + a[q].y*a[q].y + a[q].z*a[q].z + a[q].w*a[q].w;
        }
        #pragma unroll
        for (int o = 16; o > 0; o >>= 1) {
            s  += __shfl_xor_sync(0xffffffffu, s,  o);
            sq += __shfl_xor_sync(0xffffffffu, sq, o);
        }
        float mu   = s * (1.0f / (float)D_MODEL);
        float var  = sq * (1.0f / (float)D_MODEL) - mu * mu;
        float istd = rsqrtf(var + LN_EPS);

        const float4* wp = reinterpret_cast<const float4*>(ln_w);
        const float4* bp = reinterpret_cast<const float4*>(ln_b);
        float4* shp = reinterpret_cast<float4*>(sh) + lr * (D_MODEL / 4);
        #pragma unroll
        for (int q = 0; q < 4; q++) {
            float4 w4 = wp[lane + 32 * q];
            float4 b4 = bp[lane + 32 * q];
            float4 nv;
            nv.x = (a[q].x - mu) * istd * w4.x + b4.x;
            nv.y = (a[q].y - mu) * istd * w4.y + b4.y;
            nv.z = (a[q].z - mu) * istd * w4.z + b4.z;
            nv.w = (a[q].w - mu) * istd * w4.w + b4.w;
            shp[lane + 32 * q] = nv;
        }
    }
    __syncthreads();

    int tx = t & 31;
    int ty = t >> 5;
    int r0 = ty * 2, r1 = r0 + 1;

    float acc[8];
    #pragma unroll
    for (int q = 0; q < 8; q++) acc[q] = 0.0f;

    const float* sh0 = sh + r0 * D_MODEL;
    const float* sh1 = sh + r1 * D_MODEL;

    #pragma unroll 4
    for (int c = 0; c < D_MODEL; c++) {
        float4 w = *reinterpret_cast<const float4*>(g_Wt + c * 128 + tx * 4);
        float h0 = sh0[c];
        float h1 = sh1[c];
        acc[0] = fmaf(h0, w.x, acc[0]);
        acc[1] = fmaf(h0, w.y, acc[1]);
        acc[2] = fmaf(h0, w.z, acc[2]);
        acc[3] = fmaf(h0, w.w, acc[3]);
        acc[4] = fmaf(h1, w.x, acc[4]);
        acc[5] = fmaf(h1, w.y, acc[5]);
        acc[6] = fmaf(h1, w.z, acc[6]);
        acc[7] = fmaf(h1, w.w, acc[7]);
    }

    size_t grow0 = (size_t)blockIdx.x * TR + r0;
    size_t grow1 = grow0 + 1;
    int col = tx * 4;
    if (col < D_LOW) {
        float4 b = *reinterpret_cast<const float4*>(wu_b + col);
        float4 o0 = make_float4(acc[0] + b.x, acc[1] + b.y, acc[2] + b.z, acc[3] + b.w);
        float4 o1 = make_float4(acc[4] + b.x, acc[5] + b.y, acc[6] + b.z, acc[7] + b.w);
        *reinterpret_cast<float4*>(g_U + grow0 * D_LOW + col) = o0;
        *reinterpret_cast<float4*>(g_U + grow1 * D_LOW + col) = o1;
    } else {
        int vc = col - D_LOW;
        float4 b = *reinterpret_cast<const float4*>(wv_b + vc);
        float v0x = acc[0] + b.x, v0y = acc[1] + b.y, v0z = acc[2] + b.z, v0w = acc[3] + b.w;
        float v1x = acc[4] + b.x, v1y = acc[5] + b.y, v1z = acc[6] + b.z, v1w = acc[7] + b.w;
        uint32_t lo, hi;
        CVT_BF2(lo, v0x, v0y); CVT_BF2(hi, v0z, v0w);
        g_Vb[grow0 * 16 + (vc >> 2)] = (unsigned long long)lo | ((unsigned long long)hi << 32);
        CVT_BF2(lo, v1x, v1y); CVT_BF2(hi, v1z, v1w);
        g_Vb[grow1 * 16 + (vc >> 2)] = (unsigned long long)lo | ((unsigned long long)hi << 32);
    }
}

// ---------------------------------------------------------------------------
// Kernel 2: mma.sync bilinear, A-fragments built in registers from s_V
// (no W smem tile, no ldmatrix), bias folded into accumulator init.
// CTA = one token i; warp = 32 pairs/chunk; last CTA finalizes.
// ---------------------------------------------------------------------------
#define DSTRIDE 41            // floats per D row
#define VW 36                 // words per s_V row (9 uint4)

__global__ void __launch_bounds__(128) main_kernel(
    const float* __restrict__ x_true, const float* __restrict__ pad,
    const float* __restrict__ wb_w,  const float* __restrict__ wb_b,
    int B, int N, float* __restrict__ out, int total_ctas)
{
    __shared__ uint4 s_V[JT * 9];                 // 18432 B
    __shared__ float s_D[4][32 * DSTRIDE];        // 20992 B
    __shared__ uint32_t s_Wb[NB_PAD * 32];        // 5120 B
    __shared__ uint32_t s_U[32];
    __shared__ float s_wbb[NB_PAD];
    __shared__ float s_xi[4];
    __shared__ float s_red[4];
    __shared__ unsigned s_redc[4];

    int tid  = threadIdx.x;
    int wid  = tid >> 5;
    int lane = tid & 31;
    int g    = lane >> 2;       // group row (0..7)
    int tig  = lane & 3;        // thread in group (0..3)
    int r = blockIdx.x;         // b*N + i
    int b = r / N;

    for (int idx = tid; idx < NB_PAD * 32; idx += 128) {
        int row = idx >> 5, cp = idx & 31;
        float f0 = 0.0f, f1 = 0.0f;
        if (row < NUM_BINS) {
            f0 = wb_w[row * D_LOW + cp * 2];
            f1 = wb_w[row * D_LOW + cp * 2 + 1];
        }
        uint32_t v; CVT_BF2(v, f0, f1);
        s_Wb[idx] = v;
    }
    if (tid < 32) {
        float f0 = g_U[(size_t)r * D_LOW + tid * 2];
        float f1 = g_U[(size_t)r * D_LOW + tid * 2 + 1];
        uint32_t v; CVT_BF2(v, f0, f1);
        s_U[tid] = v;
    }
    if (tid < NB_PAD) s_wbb[tid] = (tid < NUM_BINS) ? wb_b[tid] : 0.0f;
    if (tid == 0) {
        size_t xb = (size_t)r * 3;
        s_xi[0] = x_true[xb]; s_xi[1] = x_true[xb + 1]; s_xi[2] = x_true[xb + 2];
        s_xi[3] = pad[r];
    }
    __syncthreads();

    // B fragments (constant across all chunks)
    uint32_t breg[40];
    #pragma unroll
    for (int ks = 0; ks < 4; ks++) {
        #pragma unroll
        for (int nt = 0; nt < 5; nt++) {
            int row = nt * 8 + g;
            int cp  = ks * 8 + tig;
            breg[ks * 10 + nt * 2 + 0] = s_Wb[row * 32 + cp];
            breg[ks * 10 + nt * 2 + 1] = s_Wb[row * 32 + cp + 4];
        }
    }
    // U words this lane ever needs: words ks*8+tig and ks*8+tig+4
    uint32_t ureg[8];
    #pragma unroll
    for (int ks = 0; ks < 4; ks++) {
        ureg[2 * ks + 0] = s_U[ks * 8 + tig];
        ureg[2 * ks + 1] = s_U[ks * 8 + tig + 4];
    }
    // bias for this lane's D columns: col = nt*8 + 2*tig (+1)
    float bias0[5], bias1[5];
    #pragma unroll
    for (int nt = 0; nt < 5; nt++) {
        bias0[nt] = s_wbb[nt * 8 + 2 * tig];
        bias1[nt] = s_wbb[nt * 8 + 2 * tig + 1];
    }

    float xi0 = s_xi[0], xi1 = s_xi[1], xi2 = s_xi[2], pi = s_xi[3];
    float* sDw = s_D[wid];
    const uint32_t* sv32 = reinterpret_cast<const uint32_t*>(s_V);

    float cv = 0.0f; unsigned cc = 0u;
    int nchunks = (N + JT - 1) / JT;

    for (int jc = 0; jc < nchunks; jc++) {
        __syncwarp();
        int jw = jc * JT + wid * 32;      // this warp's first j

        // stage V rows jw..jw+31 (coalesced: 8 lanes per 128B row)
        {
            const uint4* src = reinterpret_cast<const uint4*>(g_Vb) + ((size_t)b * N) * 8;
            #pragma unroll
            for (int it = 0; it < 8; it++) {
                int idx = it * 32 + lane;
                int row = idx >> 3, q = idx & 7;
                int j = jw + row;
                uint4 v = make_uint4(0u, 0u, 0u, 0u);
                if (j < N) v = src[(size_t)j * 8 + q];
                s_V[(wid * 32 + row) * 9 + q] = v;
            }
        }
        __syncwarp();

        // acc init = bias (folds wb_b into the GEMM)
        float acc[2][5][4];
        #pragma unroll
        for (int m = 0; m < 2; m++)
            #pragma unroll
            for (int nt = 0; nt < 5; nt++) {
                acc[m][nt][0] = bias0[nt];
                acc[m][nt][1] = bias1[nt];
                acc[m][nt][2] = bias0[nt];
                acc[m][nt][3] = bias1[nt];
            }

        // A-fragments built in registers: V word (conflict-free LDS.32) * U word
        #pragma unroll
        for (int m = 0; m < 2; m++) {
            int row0 = wid * 32 + m * 16 + g;      // rows g / g+8 of this m-tile
            #pragma unroll
            for (int ks = 0; ks < 4; ks++) {
                int w0 = row0 * VW + ks * 8 + tig;
                uint32_t a0 = sv32[w0];
                uint32_t a1 = sv32[w0 + 8 * VW];
                uint32_t a2 = sv32[w0 + 4];
                uint32_t a3 = sv32[w0 + 8 * VW + 4];
                MULBF2(a0, a0, ureg[2 * ks]);
                MULBF2(a1, a1, ureg[2 * ks]);
                MULBF2(a2, a2, ureg[2 * ks + 1]);
                MULBF2(a3, a3, ureg[2 * ks + 1]);
                #pragma unroll
                for (int nt = 0; nt < 5; nt++)
                    MMA_BF16(acc[m][nt], a0, a1, a2, a3,
                             breg[ks * 10 + nt * 2], breg[ks * 10 + nt * 2 + 1]);
            }
        }
        __syncwarp();

        // D -> smem (pair-major, 41-float stride); bias already included
        #pragma unroll
        for (int m = 0; m < 2; m++) {
            int p0 = m * 16 + g;
            #pragma unroll
            for (int nt = 0; nt < 5; nt++) {
                int col = nt * 8 + tig * 2;
                sDw[p0 * DSTRIDE + col]           = acc[m][nt][0];
                sDw[p0 * DSTRIDE + col + 1]       = acc[m][nt][1];
                sDw[(p0 + 8) * DSTRIDE + col]     = acc[m][nt][2];
                sDw[(p0 + 8) * DSTRIDE + col + 1] = acc[m][nt][3];
            }
        }
        __syncwarp();

        // epilogue: pair = lane, single-pass maxless logsumexp
        int j = jw + lane;
        float xj0 = 0.f, xj1 = 0.f, xj2 = 0.f, pj = 0.f;
        if (j < N) {
            size_t xb = ((size_t)b * N + j) * 3;
            xj0 = x_true[xb]; xj1 = x_true[xb + 1]; xj2 = x_true[xb + 2];
            pj = pad[(size_t)b * N + j];
        }
        const float* lrow = sDw + lane * DSTRIDE;

        float dx = xi0 - xj0, dy = xi1 - xj1, dz = xi2 - xj2;
        float dist = sqrtf(dx * dx + dy * dy + dz * dz);
        int bin = (int)((dist - DIST_MIN_F) / BIN_W);
        bin = min(max(bin, 0), NUM_BINS - 1);

        float ssum = 0.0f, tl = 0.0f;
        #pragma unroll
        for (int k = 0; k < NUM_BINS; k++) {
            float lv = lrow[k];
            ssum += __expf(lv);
            if (k == bin) tl = lv;
        }
        float ce = __logf(ssum) - tl;

        bool ok = (j < N) && (pi * pj > 0.0f);
        cv += ok ? ce : 0.0f;
        cc += ok ? 1u : 0u;
    }

    #pragma unroll
    for (int o = 16; o > 0; o >>= 1) {
        cv += __shfl_down_sync(0xffffffffu, cv, o);
        cc += __shfl_down_sync(0xffffffffu, cc, o);
    }
    if (lane == 0) { s_red[wid] = cv; s_redc[wid] = cc; }
    __syncthreads();
    if (tid == 0) {
        float S = s_red[0] + s_red[1] + s_red[2] + s_red[3];
        unsigned C = s_redc[0] + s_redc[1] + s_redc[2] + s_redc[3];
        atomicAdd(&g_ce[b], (double)S);
        atomicAdd(&g_cnt[b], C);
        __threadfence();
        unsigned done = atomicAdd(&g_done, 1u);
        if (done == (unsigned)(total_ctas - 1)) {
            __threadfence();
            double loss = 0.0;
            int valid = 0;
            for (int bb = 0; bb < B; bb++) {
                if (g_cnt[bb] > 0u) { loss += g_ce[bb] / (double)g_cnt[bb]; valid++; }
            }
            out[0] = (float)(valid > 0 ? loss / (double)valid : 0.0);
        }
    }
}

// ---------------------------------------------------------------------------
extern "C" void kernel_launch(void* const* d_in, const int* in_sizes, int n_in,
                              void* d_out, int out_size)
{
    const float* h_res  = (const float*)d_in[0];
    const float* x_true = (const float*)d_in[1];
    const float* padm   = (const float*)d_in[2];
    const float* ln_w   = (const float*)d_in[3];
    const float* ln_b   = (const float*)d_in[4];
    const float* wu_w   = (const float*)d_in[5];
    const float* wu_b   = (const float*)d_in[6];
    const float* wv_w   = (const float*)d_in[7];
    const float* wv_b   = (const float*)d_in[8];
    const float* wb_w   = (const float*)d_in[9];
    const float* wb_b   = (const float*)d_in[10];

    int BN = in_sizes[0] / D_MODEL;   // B*N
    int B = 2;
    int N = BN / B;

    transpose_kernel<<<(D_MODEL * 128) / 256, 256>>>(wu_w, wv_w);

    prep_kernel<<<BN / TR, 256>>>(h_res, ln_w, ln_b, wu_b, wv_b);

    main_kernel<<<BN, 128>>>(x_true, padm, wb_w, wb_b, B, N, (float*)d_out, BN);
}

// round 10
// speedup vs baseline: 1.0934x; 1.0934x over previous
#include <cuda_runtime.h>
#include <cuda_bf16.h>
#include <math.h>
#include <stdint.h>

#define D_MODEL 512
#define D_LOW   64
#define NUM_BINS 39
#define NB_PAD  40
#define DIST_MIN_F 2.0f
#define DIST_MAX_F 22.0f
#define BIN_W  ((DIST_MAX_F - DIST_MIN_F) / (float)(NUM_BINS - 1))
#define LN_EPS 1e-5f
#define MAX_ROWS 4096
#define JT 128

__device__ float g_U[MAX_ROWS * D_LOW];
__device__ unsigned long long g_Vb[MAX_ROWS * (D_LOW / 4)];  // 4 bf16 per u64
__device__ float g_Wt[D_MODEL * 128];
__device__ double g_ce[8];
__device__ unsigned int g_cnt[8];
__device__ unsigned int g_done;

__device__ __forceinline__ uint32_t smem_u32(const void* p) {
    uint32_t a;
    asm("{ .reg .u64 t; cvta.to.shared.u64 t, %1; cvt.u32.u64 %0, t; }" : "=r"(a) : "l"(p));
    return a;
}
#define CVT_BF2(res, lo, hi) \
    asm("cvt.rn.satfinite.bf16x2.f32 %0, %1, %2;" : "=r"(res) : "f"(hi), "f"(lo))
#define MULBF2(res, a, b) \
    asm("mul.bf16x2 %0, %1, %2;" : "=r"(res) : "r"(a), "r"(b))

#define MMA_BF16(d, a0, a1, a2, a3, b0, b1) \
    asm volatile("mma.sync.aligned.m16n8k16.row.col.f32.bf16.bf16.f32 " \
                 "{%0,%1,%2,%3}, {%4,%5,%6,%7}, {%8,%9}, {%0,%1,%2,%3};" \
                 : "+f"((d)[0]), "+f"((d)[1]), "+f"((d)[2]), "+f"((d)[3]) \
                 : "r"(a0), "r"(a1), "r"(a2), "r"(a3), "r"(b0), "r"(b1))

// ---------------------------------------------------------------------------
// Kernel 0: transpose wu/wv into c-major Wt[512][128]; zero accumulators.
// ---------------------------------------------------------------------------
__global__ void __launch_bounds__(256) transpose_kernel(
    const float* __restrict__ wu_w, const float* __restrict__ wv_w)
{
    int idx = blockIdx.x * 256 + threadIdx.x;
    int c = idx >> 7;
    int o = idx & 127;
    float v = (o < D_LOW) ? wu_w[(size_t)o * D_MODEL + c]
                          : wv_w[(size_t)(o - D_LOW) * D_MODEL + c];
    g_Wt[idx] = v;
    if (idx < 8) { g_ce[idx] = 0.0; g_cnt[idx] = 0u; }
    if (idx == 8) g_done = 0u;
}

// ---------------------------------------------------------------------------
// Kernel 1: LayerNorm + projections. U -> fp32, V -> bf16 packed.
// ---------------------------------------------------------------------------
#define TR 16

__global__ void __launch_bounds__(256) prep_kernel(
    const float* __restrict__ h_res,
    const float* __restrict__ ln_w, const float* __restrict__ ln_b,
    const float* __restrict__ wu_b, const float* __restrict__ wv_b)
{
    __shared__ __align__(16) float sh[TR * D_MODEL];

    int t    = threadIdx.x;
    int warp = t >> 5;
    int lane = t & 31;

    #pragma unroll
    for (int rr = 0; rr < 2; rr++) {
        int lr  = warp * 2 + rr;
        size_t row = (size_t)blockIdx.x * TR + lr;
        const float4* hp = reinterpret_cast<const float4*>(h_res) + row * (D_MODEL / 4);
        float4 a[4];
        #pragma unroll
        for (int q = 0; q < 4; q++) a[q] = hp[lane + 32 * q];
        float s = 0.0f, sq = 0.0f;
        #pragma unroll
        for (int q = 0; q < 4; q++) {
            s  += a[q].x + a[q].y + a[q].z + a[q].w;
            sq += a[q].x*a[q].x + a[q].y*a[q].y + a[q].z*a[q].z + a[q].w*a[q].w;
        }
        #pragma unroll
        for (int o = 16; o > 0; o >>= 1) {
            s  += __shfl_xor_sync(0xffffffffu, s,  o);
            sq += __shfl_xor_sync(0xffffffffu, sq, o);
        }
        float mu   = s * (1.0f / (float)D_MODEL);
        float var  = sq * (1.0f / (float)D_MODEL) - mu * mu;
        float istd = rsqrtf(var + LN_EPS);

        const float4* wp = reinterpret_cast<const float4*>(ln_w);
        const float4* bp = reinterpret_cast<const float4*>(ln_b);
        float4* shp = reinterpret_cast<float4*>(sh) + lr * (D_MODEL / 4);
        #pragma unroll
        for (int q = 0; q < 4; q++) {
            float4 w4 = wp[lane + 32 * q];
            float4 b4 = bp[lane + 32 * q];
            float4 nv;
            nv.x = (a[q].x - mu) * istd * w4.x + b4.x;
            nv.y = (a[q].y - mu) * istd * w4.y + b4.y;
            nv.z = (a[q].z - mu) * istd * w4.z + b4.z;
            nv.w = (a[q].w - mu) * istd * w4.w + b4.w;
            shp[lane + 32 * q] = nv;
        }
    }
    __syncthreads();

    int tx = t & 31;
    int ty = t >> 5;
    int r0 = ty * 2, r1 = r0 + 1;

    float acc[8];
    #pragma unroll
    for (int q = 0; q < 8; q++) acc[q] = 0.0f;

    const float* sh0 = sh + r0 * D_MODEL;
    const float* sh1 = sh + r1 * D_MODEL;

    #pragma unroll 4
    for (int c = 0; c < D_MODEL; c++) {
        float4 w = *reinterpret_cast<const float4*>(g_Wt + c * 128 + tx * 4);
        float h0 = sh0[c];
        float h1 = sh1[c];
        acc[0] = fmaf(h0, w.x, acc[0]);
        acc[1] = fmaf(h0, w.y, acc[1]);
        acc[2] = fmaf(h0, w.z, acc[2]);
        acc[3] = fmaf(h0, w.w, acc[3]);
        acc[4] = fmaf(h1, w.x, acc[4]);
        acc[5] = fmaf(h1, w.y, acc[5]);
        acc[6] = fmaf(h1, w.z, acc[6]);
        acc[7] = fmaf(h1, w.w, acc[7]);
    }

    size_t grow0 = (size_t)blockIdx.x * TR + r0;
    size_t grow1 = grow0 + 1;
    int col = tx * 4;
    if (col < D_LOW) {
        float4 b = *reinterpret_cast<const float4*>(wu_b + col);
        float4 o0 = make_float4(acc[0] + b.x, acc[1] + b.y, acc[2] + b.z, acc[3] + b.w);
        float4 o1 = make_float4(acc[4] + b.x, acc[5] + b.y, acc[6] + b.z, acc[7] + b.w);
        *reinterpret_cast<float4*>(g_U + grow0 * D_LOW + col) = o0;
        *reinterpret_cast<float4*>(g_U + grow1 * D_LOW + col) = o1;
    } else {
        int vc = col - D_LOW;
        float4 b = *reinterpret_cast<const float4*>(wv_b + vc);
        float v0x = acc[0] + b.x, v0y = acc[1] + b.y, v0z = acc[2] + b.z, v0w = acc[3] + b.w;
        float v1x = acc[4] + b.x, v1y = acc[5] + b.y, v1z = acc[6] + b.z, v1w = acc[7] + b.w;
        uint32_t lo, hi;
        CVT_BF2(lo, v0x, v0y); CVT_BF2(hi, v0z, v0w);
        g_Vb[grow0 * 16 + (vc >> 2)] = (unsigned long long)lo | ((unsigned long long)hi << 32);
        CVT_BF2(lo, v1x, v1y); CVT_BF2(hi, v1z, v1w);
        g_Vb[grow1 * 16 + (vc >> 2)] = (unsigned long long)lo | ((unsigned long long)hi << 32);
    }
}

// ---------------------------------------------------------------------------
// Kernel 2: mma.sync bilinear, TWO tokens per CTA sharing the staged V chunk.
// A-fragments built in registers; bias folded into acc init; maxless lse.
// ---------------------------------------------------------------------------
#define DSTRIDE 41            // floats per D row
#define VW 36                 // words per s_V row (9 uint4)

__global__ void __launch_bounds__(128) main_kernel(
    const float* __restrict__ x_true, const float* __restrict__ pad,
    const float* __restrict__ wb_w,  const float* __restrict__ wb_b,
    int B, int N, float* __restrict__ out, int total_ctas)
{
    __shared__ uint4 s_V[JT * 9];                 // 18432 B
    __shared__ float s_D[4][32 * DSTRIDE];        // 20992 B
    __shared__ uint32_t s_Wb[NB_PAD * 32];        // 5120 B
    __shared__ uint32_t s_U[64];                  // 2 tokens x 32 bf16x2
    __shared__ float s_wbb[NB_PAD];
    __shared__ float s_xi[8];                     // 2 tokens x (x,y,z,pad)
    __shared__ float s_red[4];
    __shared__ unsigned s_redc[4];

    int tid  = threadIdx.x;
    int wid  = tid >> 5;
    int lane = tid & 31;
    int g    = lane >> 2;       // group row (0..7)
    int tig  = lane & 3;        // thread in group (0..3)
    int r0 = blockIdx.x * 2;    // first token row (b*N + i), N even
    int b  = r0 / N;

    for (int idx = tid; idx < NB_PAD * 32; idx += 128) {
        int row = idx >> 5, cp = idx & 31;
        float f0 = 0.0f, f1 = 0.0f;
        if (row < NUM_BINS) {
            f0 = wb_w[row * D_LOW + cp * 2];
            f1 = wb_w[row * D_LOW + cp * 2 + 1];
        }
        uint32_t v; CVT_BF2(v, f0, f1);
        s_Wb[idx] = v;
    }
    if (tid < 64) {
        int tok = tid >> 5, w = tid & 31;
        float f0 = g_U[(size_t)(r0 + tok) * D_LOW + w * 2];
        float f1 = g_U[(size_t)(r0 + tok) * D_LOW + w * 2 + 1];
        uint32_t v; CVT_BF2(v, f0, f1);
        s_U[tid] = v;
    }
    if (tid < NB_PAD) s_wbb[tid] = (tid < NUM_BINS) ? wb_b[tid] : 0.0f;
    if (tid < 2) {
        size_t xb = (size_t)(r0 + tid) * 3;
        s_xi[tid * 4 + 0] = x_true[xb];
        s_xi[tid * 4 + 1] = x_true[xb + 1];
        s_xi[tid * 4 + 2] = x_true[xb + 2];
        s_xi[tid * 4 + 3] = pad[r0 + tid];
    }
    __syncthreads();

    // B fragments (constant across all chunks and both tokens)
    uint32_t breg[40];
    #pragma unroll
    for (int ks = 0; ks < 4; ks++) {
        #pragma unroll
        for (int nt = 0; nt < 5; nt++) {
            int row = nt * 8 + g;
            int cp  = ks * 8 + tig;
            breg[ks * 10 + nt * 2 + 0] = s_Wb[row * 32 + cp];
            breg[ks * 10 + nt * 2 + 1] = s_Wb[row * 32 + cp + 4];
        }
    }
    // U words per token: words ks*8+tig and ks*8+tig+4
    uint32_t ureg[2][8];
    #pragma unroll
    for (int tok = 0; tok < 2; tok++)
        #pragma unroll
        for (int ks = 0; ks < 4; ks++) {
            ureg[tok][2 * ks + 0] = s_U[tok * 32 + ks * 8 + tig];
            ureg[tok][2 * ks + 1] = s_U[tok * 32 + ks * 8 + tig + 4];
        }
    // bias for this lane's D columns
    float bias0[5], bias1[5];
    #pragma unroll
    for (int nt = 0; nt < 5; nt++) {
        bias0[nt] = s_wbb[nt * 8 + 2 * tig];
        bias1[nt] = s_wbb[nt * 8 + 2 * tig + 1];
    }
    float xi[2][4];
    #pragma unroll
    for (int tok = 0; tok < 2; tok++)
        #pragma unroll
        for (int q = 0; q < 4; q++) xi[tok][q] = s_xi[tok * 4 + q];

    float* sDw = s_D[wid];
    const uint32_t* sv32 = reinterpret_cast<const uint32_t*>(s_V);

    float cv = 0.0f; unsigned cc = 0u;
    int nchunks = (N + JT - 1) / JT;

    for (int jc = 0; jc < nchunks; jc++) {
        __syncwarp();
        int jw = jc * JT + wid * 32;      // this warp's first j

        // stage V rows jw..jw+31 (coalesced: 8 lanes per 128B row)
        {
            const uint4* src = reinterpret_cast<const uint4*>(g_Vb) + ((size_t)b * N) * 8;
            #pragma unroll
            for (int it = 0; it < 8; it++) {
                int idx = it * 32 + lane;
                int row = idx >> 3, q = idx & 7;
                int j = jw + row;
                uint4 v = make_uint4(0u, 0u, 0u, 0u);
                if (j < N) v = src[(size_t)j * 8 + q];
                s_V[(wid * 32 + row) * 9 + q] = v;
            }
        }

        // j-coordinates loaded once, reused by both tokens
        int j = jw + lane;
        float xj0 = 0.f, xj1 = 0.f, xj2 = 0.f, pj = 0.f;
        if (j < N) {
            size_t xb = ((size_t)b * N + j) * 3;
            xj0 = x_true[xb]; xj1 = x_true[xb + 1]; xj2 = x_true[xb + 2];
            pj = pad[(size_t)b * N + j];
        }
        __syncwarp();

        #pragma unroll
        for (int tok = 0; tok < 2; tok++) {
            // acc init = bias (folds wb_b into the GEMM)
            float acc[2][5][4];
            #pragma unroll
            for (int m = 0; m < 2; m++)
                #pragma unroll
                for (int nt = 0; nt < 5; nt++) {
                    acc[m][nt][0] = bias0[nt];
                    acc[m][nt][1] = bias1[nt];
                    acc[m][nt][2] = bias0[nt];
                    acc[m][nt][3] = bias1[nt];
                }

            // A-fragments: V word (conflict-free LDS.32) * U word
            #pragma unroll
            for (int m = 0; m < 2; m++) {
                int row0 = wid * 32 + m * 16 + g;
                #pragma unroll
                for (int ks = 0; ks < 4; ks++) {
                    int w0 = row0 * VW + ks * 8 + tig;
                    uint32_t a0 = sv32[w0];
                    uint32_t a1 = sv32[w0 + 8 * VW];
                    uint32_t a2 = sv32[w0 + 4];
                    uint32_t a3 = sv32[w0 + 8 * VW + 4];
                    MULBF2(a0, a0, ureg[tok][2 * ks]);
                    MULBF2(a1, a1, ureg[tok][2 * ks]);
                    MULBF2(a2, a2, ureg[tok][2 * ks + 1]);
                    MULBF2(a3, a3, ureg[tok][2 * ks + 1]);
                    #pragma unroll
                    for (int nt = 0; nt < 5; nt++)
                        MMA_BF16(acc[m][nt], a0, a1, a2, a3,
                                 breg[ks * 10 + nt * 2], breg[ks * 10 + nt * 2 + 1]);
                }
            }
            __syncwarp();

            // D -> smem (pair-major, 41-float stride)
            #pragma unroll
            for (int m = 0; m < 2; m++) {
                int p0 = m * 16 + g;
                #pragma unroll
                for (int nt = 0; nt < 5; nt++) {
                    int col = nt * 8 + tig * 2;
                    sDw[p0 * DSTRIDE + col]           = acc[m][nt][0];
                    sDw[p0 * DSTRIDE + col + 1]       = acc[m][nt][1];
                    sDw[(p0 + 8) * DSTRIDE + col]     = acc[m][nt][2];
                    sDw[(p0 + 8) * DSTRIDE + col + 1] = acc[m][nt][3];
                }
            }
            __syncwarp();

            // epilogue: pair = lane, single-pass maxless logsumexp
            const float* lrow = sDw + lane * DSTRIDE;
            float dx = xi[tok][0] - xj0, dy = xi[tok][1] - xj1, dz = xi[tok][2] - xj2;
            float dist = sqrtf(dx * dx + dy * dy + dz * dz);
            int bin = (int)((dist - DIST_MIN_F) / BIN_W);
            bin = min(max(bin, 0), NUM_BINS - 1);

            float ssum = 0.0f, tl = 0.0f;
            #pragma unroll
            for (int k = 0; k < NUM_BINS; k++) {
                float lv = lrow[k];
                ssum += __expf(lv);
                if (k == bin) tl = lv;
            }
            float ce = __logf(ssum) - tl;

            bool ok = (j < N) && (xi[tok][3] * pj > 0.0f);
            cv += ok ? ce : 0.0f;
            cc += ok ? 1u : 0u;
            __syncwarp();
        }
    }

    #pragma unroll
    for (int o = 16; o > 0; o >>= 1) {
        cv += __shfl_down_sync(0xffffffffu, cv, o);
        cc += __shfl_down_sync(0xffffffffu, cc, o);
    }
    if (lane == 0) { s_red[wid] = cv; s_redc[wid] = cc; }
    __syncthreads();
    if (tid == 0) {
        float S = s_red[0] + s_red[1] + s_red[2] + s_red[3];
        unsigned C = s_redc[0] + s_redc[1] + s_redc[2] + s_redc[3];
        atomicAdd(&g_ce[b], (double)S);
        atomicAdd(&g_cnt[b], C);
        __threadfence();
        unsigned done = atomicAdd(&g_done, 1u);
        if (done == (unsigned)(total_ctas - 1)) {
            __threadfence();
            double loss = 0.0;
            int valid = 0;
            for (int bb = 0; bb < B; bb++) {
                if (g_cnt[bb] > 0u) { loss += g_ce[bb] / (double)g_cnt[bb]; valid++; }
            }
            out[0] = (float)(valid > 0 ? loss / (double)valid : 0.0);
        }
    }
}

// ---------------------------------------------------------------------------
extern "C" void kernel_launch(void* const* d_in, const int* in_sizes, int n_in,
                              void* d_out, int out_size)
{
    const float* h_res  = (const float*)d_in[0];
    const float* x_true = (const float*)d_in[1];
    const float* padm   = (const float*)d_in[2];
    const float* ln_w   = (const float*)d_in[3];
    const float* ln_b   = (const float*)d_in[4];
    const float* wu_w   = (const float*)d_in[5];
    const float* wu_b   = (const float*)d_in[6];
    const float* wv_w   = (const float*)d_in[7];
    const float* wv_b   = (const float*)d_in[8];
    const float* wb_w   = (const float*)d_in[9];
    const float* wb_b   = (const float*)d_in[10];

    int BN = in_sizes[0] / D_MODEL;   // B*N
    int B = 2;
    int N = BN / B;

    transpose_kernel<<<(D_MODEL * 128) / 256, 256>>>(wu_w, wv_w);

    prep_kernel<<<BN / TR, 256>>>(h_res, ln_w, ln_b, wu_b, wv_b);

    main_kernel<<<BN / 2, 128>>>(x_true, padm, wb_w, wb_b, B, N, (float*)d_out, BN / 2);
}

// round 11
// speedup vs baseline: 1.2233x; 1.1188x over previous
#include <cuda_runtime.h>
#include <cuda_bf16.h>
#include <math.h>
#include <stdint.h>

#define D_MODEL 512
#define D_LOW   64
#define NUM_BINS 39
#define NB_PAD  40
#define DIST_MIN_F 2.0f
#define DIST_MAX_F 22.0f
#define BIN_W  ((DIST_MAX_F - DIST_MIN_F) / (float)(NUM_BINS - 1))
#define LN_EPS 1e-5f
#define MAX_ROWS 4096
#define JT 128
#define TOK 4                  // tokens per CTA

__device__ float g_U[MAX_ROWS * D_LOW];
__device__ unsigned long long g_Vb[MAX_ROWS * (D_LOW / 4)];  // 4 bf16 per u64
__device__ float g_Wt[D_MODEL * 128];
__device__ double g_ce[8];
__device__ unsigned int g_cnt[8];
__device__ unsigned int g_done;

__device__ __forceinline__ uint32_t smem_u32(const void* p) {
    uint32_t a;
    asm("{ .reg .u64 t; cvta.to.shared.u64 t, %1; cvt.u32.u64 %0, t; }" : "=r"(a) : "l"(p));
    return a;
}
#define CVT_BF2(res, lo, hi) \
    asm("cvt.rn.satfinite.bf16x2.f32 %0, %1, %2;" : "=r"(res) : "f"(hi), "f"(lo))
#define MULBF2(res, a, b) \
    asm("mul.bf16x2 %0, %1, %2;" : "=r"(res) : "r"(a), "r"(b))

#define MMA_BF16(d, a0, a1, a2, a3, b0, b1) \
    asm volatile("mma.sync.aligned.m16n8k16.row.col.f32.bf16.bf16.f32 " \
                 "{%0,%1,%2,%3}, {%4,%5,%6,%7}, {%8,%9}, {%0,%1,%2,%3};" \
                 : "+f"((d)[0]), "+f"((d)[1]), "+f"((d)[2]), "+f"((d)[3]) \
                 : "r"(a0), "r"(a1), "r"(a2), "r"(a3), "r"(b0), "r"(b1))

// ---------------------------------------------------------------------------
// Kernel 0: transpose wu/wv into c-major Wt[512][128]; zero accumulators.
// ---------------------------------------------------------------------------
__global__ void __launch_bounds__(256) transpose_kernel(
    const float* __restrict__ wu_w, const float* __restrict__ wv_w)
{
    int idx = blockIdx.x * 256 + threadIdx.x;
    int c = idx >> 7;
    int o = idx & 127;
    float v = (o < D_LOW) ? wu_w[(size_t)o * D_MODEL + c]
                          : wv_w[(size_t)(o - D_LOW) * D_MODEL + c];
    g_Wt[idx] = v;
    if (idx < 8) { g_ce[idx] = 0.0; g_cnt[idx] = 0u; }
    if (idx == 8) g_done = 0u;
}

// ---------------------------------------------------------------------------
// Kernel 1: LayerNorm + projections. U -> fp32, V -> bf16 packed.
// ---------------------------------------------------------------------------
#define TR 16

__global__ void __launch_bounds__(256) prep_kernel(
    const float* __restrict__ h_res,
    const float* __restrict__ ln_w, const float* __restrict__ ln_b,
    const float* __restrict__ wu_b, const float* __restrict__ wv_b)
{
    __shared__ __align__(16) float sh[TR * D_MODEL];

    int t    = threadIdx.x;
    int warp = t >> 5;
    int lane = t & 31;

    #pragma unroll
    for (int rr = 0; rr < 2; rr++) {
        int lr  = warp * 2 + rr;
        size_t row = (size_t)blockIdx.x * TR + lr;
        const float4* hp = reinterpret_cast<const float4*>(h_res) + row * (D_MODEL / 4);
        float4 a[4];
        #pragma unroll
        for (int q = 0; q < 4; q++) a[q] = hp[lane + 32 * q];
        float s = 0.0f, sq = 0.0f;
        #pragma unroll
        for (int q = 0; q < 4; q++) {
            s  += a[q].x + a[q].y + a[q].z + a[q].w;
            sq += a[q].x*a[q].x + a[q].y*a[q].y + a[q].z*a[q].z + a[q].w*a[q].w;
        }
        #pragma unroll
        for (int o = 16; o > 0; o >>= 1) {
            s  += __shfl_xor_sync(0xffffffffu, s,  o);
            sq += __shfl_xor_sync(0xffffffffu, sq, o);
        }
        float mu   = s * (1.0f / (float)D_MODEL);
        float var  = sq * (1.0f / (float)D_MODEL) - mu * mu;
        float istd = rsqrtf(var + LN_EPS);

        const float4* wp = reinterpret_cast<const float4*>(ln_w);
        const float4* bp = reinterpret_cast<const float4*>(ln_b);
        float4* shp = reinterpret_cast<float4*>(sh) + lr * (D_MODEL / 4);
        #pragma unroll
        for (int q = 0; q < 4; q++) {
            float4 w4 = wp[lane + 32 * q];
            float4 b4 = bp[lane + 32 * q];
            float4 nv;
            nv.x = (a[q].x - mu) * istd * w4.x + b4.x;
            nv.y = (a[q].y - mu) * istd * w4.y + b4.y;
            nv.z = (a[q].z - mu) * istd * w4.z + b4.z;
            nv.w = (a[q].w - mu) * istd * w4.w + b4.w;
            shp[lane + 32 * q] = nv;
        }
    }
    __syncthreads();

    int tx = t & 31;
    int ty = t >> 5;
    int r0 = ty * 2, r1 = r0 + 1;

    float acc[8];
    #pragma unroll
    for (int q = 0; q < 8; q++) acc[q] = 0.0f;

    const float* sh0 = sh + r0 * D_MODEL;
    const float* sh1 = sh + r1 * D_MODEL;

    #pragma unroll 4
    for (int c = 0; c < D_MODEL; c++) {
        float4 w = *reinterpret_cast<const float4*>(g_Wt + c * 128 + tx * 4);
        float h0 = sh0[c];
        float h1 = sh1[c];
        acc[0] = fmaf(h0, w.x, acc[0]);
        acc[1] = fmaf(h0, w.y, acc[1]);
        acc[2] = fmaf(h0, w.z, acc[2]);
        acc[3] = fmaf(h0, w.w, acc[3]);
        acc[4] = fmaf(h1, w.x, acc[4]);
        acc[5] = fmaf(h1, w.y, acc[5]);
        acc[6] = fmaf(h1, w.z, acc[6]);
        acc[7] = fmaf(h1, w.w, acc[7]);
    }

    size_t grow0 = (size_t)blockIdx.x * TR + r0;
    size_t grow1 = grow0 + 1;
    int col = tx * 4;
    if (col < D_LOW) {
        float4 b = *reinterpret_cast<const float4*>(wu_b + col);
        float4 o0 = make_float4(acc[0] + b.x, acc[1] + b.y, acc[2] + b.z, acc[3] + b.w);
        float4 o1 = make_float4(acc[4] + b.x, acc[5] + b.y, acc[6] + b.z, acc[7] + b.w);
        *reinterpret_cast<float4*>(g_U + grow0 * D_LOW + col) = o0;
        *reinterpret_cast<float4*>(g_U + grow1 * D_LOW + col) = o1;
    } else {
        int vc = col - D_LOW;
        float4 b = *reinterpret_cast<const float4*>(wv_b + vc);
        float v0x = acc[0] + b.x, v0y = acc[1] + b.y, v0z = acc[2] + b.z, v0w = acc[3] + b.w;
        float v1x = acc[4] + b.x, v1y = acc[5] + b.y, v1z = acc[6] + b.z, v1w = acc[7] + b.w;
        uint32_t lo, hi;
        CVT_BF2(lo, v0x, v0y); CVT_BF2(hi, v0z, v0w);
        g_Vb[grow0 * 16 + (vc >> 2)] = (unsigned long long)lo | ((unsigned long long)hi << 32);
        CVT_BF2(lo, v1x, v1y); CVT_BF2(hi, v1z, v1w);
        g_Vb[grow1 * 16 + (vc >> 2)] = (unsigned long long)lo | ((unsigned long long)hi << 32);
    }
}

// ---------------------------------------------------------------------------
// Kernel 2: mma.sync bilinear, FOUR tokens per CTA sharing each staged V
// chunk. A-fragments built in registers; bias folded into acc init;
// maxless logsumexp; last CTA finalizes the scalar.
// ---------------------------------------------------------------------------
#define DSTRIDE 41            // floats per D row (odd -> conflict-free scalar LDS)
#define VW 36                 // words per s_V row (9 uint4)

__global__ void __launch_bounds__(128) main_kernel(
    const float* __restrict__ x_true, const float* __restrict__ pad,
    const float* __restrict__ wb_w,  const float* __restrict__ wb_b,
    int B, int N, float* __restrict__ out, int total_ctas)
{
    __shared__ uint4 s_V[JT * 9];                 // 18432 B
    __shared__ float s_D[4][32 * DSTRIDE];        // 20992 B
    __shared__ uint32_t s_Wb[NB_PAD * 32];        // 5120 B
    __shared__ uint32_t s_U[TOK * 32];            // 4 tokens x 32 bf16x2
    __shared__ float s_wbb[NB_PAD];
    __shared__ float s_xi[TOK * 4];               // 4 tokens x (x,y,z,pad)
    __shared__ float s_red[4];
    __shared__ unsigned s_redc[4];

    int tid  = threadIdx.x;
    int wid  = tid >> 5;
    int lane = tid & 31;
    int g    = lane >> 2;       // group row (0..7)
    int tig  = lane & 3;        // thread in group (0..3)
    int r0 = blockIdx.x * TOK;  // first token row (b*N + i); N % TOK == 0
    int b  = r0 / N;

    for (int idx = tid; idx < NB_PAD * 32; idx += 128) {
        int row = idx >> 5, cp = idx & 31;
        float f0 = 0.0f, f1 = 0.0f;
        if (row < NUM_BINS) {
            f0 = wb_w[row * D_LOW + cp * 2];
            f1 = wb_w[row * D_LOW + cp * 2 + 1];
        }
        uint32_t v; CVT_BF2(v, f0, f1);
        s_Wb[idx] = v;
    }
    if (tid < TOK * 32) {
        int tok = tid >> 5, w = tid & 31;
        float f0 = g_U[(size_t)(r0 + tok) * D_LOW + w * 2];
        float f1 = g_U[(size_t)(r0 + tok) * D_LOW + w * 2 + 1];
        uint32_t v; CVT_BF2(v, f0, f1);
        s_U[tid] = v;
    }
    if (tid < NB_PAD) s_wbb[tid] = (tid < NUM_BINS) ? wb_b[tid] : 0.0f;
    if (tid < TOK) {
        size_t xb = (size_t)(r0 + tid) * 3;
        s_xi[tid * 4 + 0] = x_true[xb];
        s_xi[tid * 4 + 1] = x_true[xb + 1];
        s_xi[tid * 4 + 2] = x_true[xb + 2];
        s_xi[tid * 4 + 3] = pad[r0 + tid];
    }
    __syncthreads();

    // B fragments (constant across all chunks and tokens)
    uint32_t breg[40];
    #pragma unroll
    for (int ks = 0; ks < 4; ks++) {
        #pragma unroll
        for (int nt = 0; nt < 5; nt++) {
            int row = nt * 8 + g;
            int cp  = ks * 8 + tig;
            breg[ks * 10 + nt * 2 + 0] = s_Wb[row * 32 + cp];
            breg[ks * 10 + nt * 2 + 1] = s_Wb[row * 32 + cp + 4];
        }
    }
    // bias for this lane's D columns
    float bias0[5], bias1[5];
    #pragma unroll
    for (int nt = 0; nt < 5; nt++) {
        bias0[nt] = s_wbb[nt * 8 + 2 * tig];
        bias1[nt] = s_wbb[nt * 8 + 2 * tig + 1];
    }

    float* sDw = s_D[wid];
    const uint32_t* sv32 = reinterpret_cast<const uint32_t*>(s_V);

    float cv = 0.0f; unsigned cc = 0u;
    int nchunks = (N + JT - 1) / JT;

    for (int jc = 0; jc < nchunks; jc++) {
        __syncwarp();
        int jw = jc * JT + wid * 32;      // this warp's first j

        // stage V rows jw..jw+31 (coalesced: 8 lanes per 128B row)
        {
            const uint4* src = reinterpret_cast<const uint4*>(g_Vb) + ((size_t)b * N) * 8;
            #pragma unroll
            for (int it = 0; it < 8; it++) {
                int idx = it * 32 + lane;
                int row = idx >> 3, q = idx & 7;
                int j = jw + row;
                uint4 v = make_uint4(0u, 0u, 0u, 0u);
                if (j < N) v = src[(size_t)j * 8 + q];
                s_V[(wid * 32 + row) * 9 + q] = v;
            }
        }

        // j-coordinates loaded once, reused by all tokens
        int j = jw + lane;
        float xj0 = 0.f, xj1 = 0.f, xj2 = 0.f, pj = 0.f;
        if (j < N) {
            size_t xb = ((size_t)b * N + j) * 3;
            xj0 = x_true[xb]; xj1 = x_true[xb + 1]; xj2 = x_true[xb + 2];
            pj = pad[(size_t)b * N + j];
        }
        __syncwarp();

        #pragma unroll
        for (int tok = 0; tok < TOK; tok++) {
            // U words for this token (from smem; keeps register count flat)
            uint32_t ureg[8];
            #pragma unroll
            for (int ks = 0; ks < 4; ks++) {
                ureg[2 * ks + 0] = s_U[tok * 32 + ks * 8 + tig];
                ureg[2 * ks + 1] = s_U[tok * 32 + ks * 8 + tig + 4];
            }

            // acc init = bias (folds wb_b into the GEMM)
            float acc[2][5][4];
            #pragma unroll
            for (int m = 0; m < 2; m++)
                #pragma unroll
                for (int nt = 0; nt < 5; nt++) {
                    acc[m][nt][0] = bias0[nt];
                    acc[m][nt][1] = bias1[nt];
                    acc[m][nt][2] = bias0[nt];
                    acc[m][nt][3] = bias1[nt];
                }

            // A-fragments: V word (conflict-free LDS.32) * U word
            #pragma unroll
            for (int m = 0; m < 2; m++) {
                int row0 = wid * 32 + m * 16 + g;
                #pragma unroll
                for (int ks = 0; ks < 4; ks++) {
                    int w0 = row0 * VW + ks * 8 + tig;
                    uint32_t a0 = sv32[w0];
                    uint32_t a1 = sv32[w0 + 8 * VW];
                    uint32_t a2 = sv32[w0 + 4];
                    uint32_t a3 = sv32[w0 + 8 * VW + 4];
                    MULBF2(a0, a0, ureg[2 * ks]);
                    MULBF2(a1, a1, ureg[2 * ks]);
                    MULBF2(a2, a2, ureg[2 * ks + 1]);
                    MULBF2(a3, a3, ureg[2 * ks + 1]);
                    #pragma unroll
                    for (int nt = 0; nt < 5; nt++)
                        MMA_BF16(acc[m][nt], a0, a1, a2, a3,
                                 breg[ks * 10 + nt * 2], breg[ks * 10 + nt * 2 + 1]);
                }
            }
            __syncwarp();

            // D -> smem (pair-major, 41-float stride)
            #pragma unroll
            for (int m = 0; m < 2; m++) {
                int p0 = m * 16 + g;
                #pragma unroll
                for (int nt = 0; nt < 5; nt++) {
                    int col = nt * 8 + tig * 2;
                    sDw[p0 * DSTRIDE + col]           = acc[m][nt][0];
                    sDw[p0 * DSTRIDE + col + 1]       = acc[m][nt][1];
                    sDw[(p0 + 8) * DSTRIDE + col]     = acc[m][nt][2];
                    sDw[(p0 + 8) * DSTRIDE + col + 1] = acc[m][nt][3];
                }
            }
            __syncwarp();

            // epilogue: pair = lane, single-pass maxless logsumexp
            const float* lrow = sDw + lane * DSTRIDE;
            float xi0 = s_xi[tok * 4 + 0];
            float xi1 = s_xi[tok * 4 + 1];
            float xi2 = s_xi[tok * 4 + 2];
            float pi  = s_xi[tok * 4 + 3];
            float dx = xi0 - xj0, dy = xi1 - xj1, dz = xi2 - xj2;
            float dist = sqrtf(dx * dx + dy * dy + dz * dz);
            int bin = (int)((dist - DIST_MIN_F) / BIN_W);
            bin = min(max(bin, 0), NUM_BINS - 1);

            float ssum = 0.0f, tl = 0.0f;
            #pragma unroll
            for (int k = 0; k < NUM_BINS; k++) {
                float lv = lrow[k];
                ssum += __expf(lv);
                if (k == bin) tl = lv;
            }
            float ce = __logf(ssum) - tl;

            bool ok = (j < N) && (pi * pj > 0.0f);
            cv += ok ? ce : 0.0f;
            cc += ok ? 1u : 0u;
            __syncwarp();
        }
    }

    #pragma unroll
    for (int o = 16; o > 0; o >>= 1) {
        cv += __shfl_down_sync(0xffffffffu, cv, o);
        cc += __shfl_down_sync(0xffffffffu, cc, o);
    }
    if (lane == 0) { s_red[wid] = cv; s_redc[wid] = cc; }
    __syncthreads();
    if (tid == 0) {
        float S = s_red[0] + s_red[1] + s_red[2] + s_red[3];
        unsigned C = s_redc[0] + s_redc[1] + s_redc[2] + s_redc[3];
        atomicAdd(&g_ce[b], (double)S);
        atomicAdd(&g_cnt[b], C);
        __threadfence();
        unsigned done = atomicAdd(&g_done, 1u);
        if (done == (unsigned)(total_ctas - 1)) {
            __threadfence();
            double loss = 0.0;
            int valid = 0;
            for (int bb = 0; bb < B; bb++) {
                if (g_cnt[bb] > 0u) { loss += g_ce[bb] / (double)g_cnt[bb]; valid++; }
            }
            out[0] = (float)(valid > 0 ? loss / (double)valid : 0.0);
        }
    }
}

// ---------------------------------------------------------------------------
extern "C" void kernel_launch(void* const* d_in, const int* in_sizes, int n_in,
                              void* d_out, int out_size)
{
    const float* h_res  = (const float*)d_in[0];
    const float* x_true = (const float*)d_in[1];
    const float* padm   = (const float*)d_in[2];
    const float* ln_w   = (const float*)d_in[3];
    const float* ln_b   = (const float*)d_in[4];
    const float* wu_w   = (const float*)d_in[5];
    const float* wu_b   = (const float*)d_in[6];
    const float* wv_w   = (const float*)d_in[7];
    const float* wv_b   = (const float*)d_in[8];
    const float* wb_w   = (const float*)d_in[9];
    const float* wb_b   = (const float*)d_in[10];

    int BN = in_sizes[0] / D_MODEL;   // B*N
    int B = 2;
    int N = BN / B;

    transpose_kernel<<<(D_MODEL * 128) / 256, 256>>>(wu_w, wv_w);

    prep_kernel<<<BN / TR, 256>>>(h_res, ln_w, ln_b, wu_b, wv_b);

    main_kernel<<<BN / TOK, 128>>>(x_true, padm, wb_w, wb_b, B, N, (float*)d_out, BN / TOK);
}

// round 12
// speedup vs baseline: 1.2635x; 1.0329x over previous
#include <cuda_runtime.h>
#include <cuda_bf16.h>
#include <math.h>
#include <stdint.h>

#define D_MODEL 512
#define D_LOW   64
#define NUM_BINS 39
#define NB_PAD  40
#define DIST_MIN_F 2.0f
#define DIST_MAX_F 22.0f
#define BIN_W  ((DIST_MAX_F - DIST_MIN_F) / (float)(NUM_BINS - 1))
#define LN_EPS 1e-5f
#define MAX_ROWS 4096
#define JT 128
#define TOK 4                  // tokens per CTA (main)

__device__ float g_U[MAX_ROWS * D_LOW];
__device__ unsigned long long g_Vb[MAX_ROWS * (D_LOW / 4)];  // 4 bf16 per u64
__device__ float g_Wt[D_MODEL * 128];
__device__ double g_ce[8];
__device__ unsigned int g_cnt[8];
__device__ unsigned int g_done;

__device__ __forceinline__ uint32_t smem_u32(const void* p) {
    uint32_t a;
    asm("{ .reg .u64 t; cvta.to.shared.u64 t, %1; cvt.u32.u64 %0, t; }" : "=r"(a) : "l"(p));
    return a;
}
#define CVT_BF2(res, lo, hi) \
    asm("cvt.rn.satfinite.bf16x2.f32 %0, %1, %2;" : "=r"(res) : "f"(hi), "f"(lo))
#define MULBF2(res, a, b) \
    asm("mul.bf16x2 %0, %1, %2;" : "=r"(res) : "r"(a), "r"(b))

#define MMA_BF16(d, a0, a1, a2, a3, b0, b1) \
    asm volatile("mma.sync.aligned.m16n8k16.row.col.f32.bf16.bf16.f32 " \
                 "{%0,%1,%2,%3}, {%4,%5,%6,%7}, {%8,%9}, {%0,%1,%2,%3};" \
                 : "+f"((d)[0]), "+f"((d)[1]), "+f"((d)[2]), "+f"((d)[3]) \
                 : "r"(a0), "r"(a1), "r"(a2), "r"(a3), "r"(b0), "r"(b1))

// ---------------------------------------------------------------------------
// Kernel 0: tiled transpose wu/wv -> c-major Wt[512][128]; coalesced both
// sides via 32x33 smem tile. Also zeroes the global accumulators.
// grid (4, 16), 256 threads.
// ---------------------------------------------------------------------------
__global__ void __launch_bounds__(256) transpose_kernel(
    const float* __restrict__ wu_w, const float* __restrict__ wv_w)
{
    __shared__ float tile[32][33];
    int o0 = blockIdx.x * 32;          // output-unit tile (rows of wu/wv)
    int c0 = blockIdx.y * 32;          // channel tile
    int tx = threadIdx.x & 31;
    int ty = threadIdx.x >> 5;         // 0..7

    #pragma unroll
    for (int i = 0; i < 4; i++) {
        int o = o0 + ty + 8 * i;
        int c = c0 + tx;
        float v = (o < D_LOW) ? wu_w[(size_t)o * D_MODEL + c]
                              : wv_w[(size_t)(o - D_LOW) * D_MODEL + c];
        tile[ty + 8 * i][tx] = v;
    }
    __syncthreads();
    #pragma unroll
    for (int i = 0; i < 4; i++) {
        int c = c0 + ty + 8 * i;
        g_Wt[(size_t)c * 128 + o0 + tx] = tile[tx][ty + 8 * i];
    }

    if (blockIdx.x == 0 && blockIdx.y == 0) {
        if (threadIdx.x < 8) { g_ce[threadIdx.x] = 0.0; g_cnt[threadIdx.x] = 0u; }
        if (threadIdx.x == 8) g_done = 0u;
    }
}

// ---------------------------------------------------------------------------
// Kernel 1: LayerNorm + projections, col-split for 2x grid parallelism.
// grid = (BN/16)*2; bid = rowblock*2 + half. half 0 -> U cols, half 1 -> V.
// 256 threads: LN warp = 2 rows (unchanged); GEMM thread = 1 row x 4 cols.
// ---------------------------------------------------------------------------
#define TR 16

__global__ void __launch_bounds__(256) prep_kernel(
    const float* __restrict__ h_res,
    const float* __restrict__ ln_w, const float* __restrict__ ln_b,
    const float* __restrict__ wu_b, const float* __restrict__ wv_b)
{
    __shared__ __align__(16) float sh[TR * D_MODEL];

    int t    = threadIdx.x;
    int warp = t >> 5;
    int lane = t & 31;
    int rb   = blockIdx.x >> 1;
    int half = blockIdx.x & 1;

    #pragma unroll
    for (int rr = 0; rr < 2; rr++) {
        int lr  = warp * 2 + rr;
        size_t row = (size_t)rb * TR + lr;
        const float4* hp = reinterpret_cast<const float4*>(h_res) + row * (D_MODEL / 4);
        float4 a[4];
        #pragma unroll
        for (int q = 0; q < 4; q++) a[q] = hp[lane + 32 * q];
        float s = 0.0f, sq = 0.0f;
        #pragma unroll
        for (int q = 0; q < 4; q++) {
            s  += a[q].x + a[q].y + a[q].z + a[q].w;
            sq += a[q].x*a[q].x + a[q].y*a[q].y + a[q].z*a[q].z + a[q].w*a[q].w;
        }
        #pragma unroll
        for (int o = 16; o > 0; o >>= 1) {
            s  += __shfl_xor_sync(0xffffffffu, s,  o);
            sq += __shfl_xor_sync(0xffffffffu, sq, o);
        }
        float mu   = s * (1.0f / (float)D_MODEL);
        float var  = sq * (1.0f / (float)D_MODEL) - mu * mu;
        float istd = rsqrtf(var + LN_EPS);

        const float4* wp = reinterpret_cast<const float4*>(ln_w);
        const float4* bp = reinterpret_cast<const float4*>(ln_b);
        float4* shp = reinterpret_cast<float4*>(sh) + lr * (D_MODEL / 4);
        #pragma unroll
        for (int q = 0; q < 4; q++) {
            float4 w4 = wp[lane + 32 * q];
            float4 b4 = bp[lane + 32 * q];
            float4 nv;
            nv.x = (a[q].x - mu) * istd * w4.x + b4.x;
            nv.y = (a[q].y - mu) * istd * w4.y + b4.y;
            nv.z = (a[q].z - mu) * istd * w4.z + b4.z;
            nv.w = (a[q].w - mu) * istd * w4.w + b4.w;
            shp[lane + 32 * q] = nv;
        }
    }
    __syncthreads();

    // GEMM: thread = (row ty, 4 cols at half*64 + tx*4)
    int ty = t >> 4;            // 0..15 row
    int tx = t & 15;            // 0..15 col group
    int col = half * 64 + tx * 4;

    float a0 = 0.0f, a1 = 0.0f, a2 = 0.0f, a3 = 0.0f;
    const float* shr = sh + ty * D_MODEL;

    #pragma unroll 4
    for (int c = 0; c < D_MODEL; c++) {
        float4 w = *reinterpret_cast<const float4*>(g_Wt + c * 128 + col);
        float h = shr[c];
        a0 = fmaf(h, w.x, a0);
        a1 = fmaf(h, w.y, a1);
        a2 = fmaf(h, w.z, a2);
        a3 = fmaf(h, w.w, a3);
    }

    size_t grow = (size_t)rb * TR + ty;
    if (half == 0) {
        float4 b = *reinterpret_cast<const float4*>(wu_b + col);
        *reinterpret_cast<float4*>(g_U + grow * D_LOW + col) =
            make_float4(a0 + b.x, a1 + b.y, a2 + b.z, a3 + b.w);
    } else {
        int vc = col - D_LOW;
        float4 b = *reinterpret_cast<const float4*>(wv_b + vc);
        float v0 = a0 + b.x, v1 = a1 + b.y, v2 = a2 + b.z, v3 = a3 + b.w;
        uint32_t lo, hi;
        CVT_BF2(lo, v0, v1); CVT_BF2(hi, v2, v3);
        g_Vb[grow * 16 + (vc >> 2)] = (unsigned long long)lo | ((unsigned long long)hi << 32);
    }
}

// ---------------------------------------------------------------------------
// Kernel 2: mma.sync bilinear, FOUR tokens per CTA sharing each staged V
// chunk (unchanged from R11 / 85.4us). Last CTA finalizes the scalar.
// ---------------------------------------------------------------------------
#define DSTRIDE 41            // floats per D row (odd -> conflict-free scalar LDS)
#define VW 36                 // words per s_V row (9 uint4)

__global__ void __launch_bounds__(128) main_kernel(
    const float* __restrict__ x_true, const float* __restrict__ pad,
    const float* __restrict__ wb_w,  const float* __restrict__ wb_b,
    int B, int N, float* __restrict__ out, int total_ctas)
{
    __shared__ uint4 s_V[JT * 9];                 // 18432 B
    __shared__ float s_D[4][32 * DSTRIDE];        // 20992 B
    __shared__ uint32_t s_Wb[NB_PAD * 32];        // 5120 B
    __shared__ uint32_t s_U[TOK * 32];            // 4 tokens x 32 bf16x2
    __shared__ float s_wbb[NB_PAD];
    __shared__ float s_xi[TOK * 4];               // 4 tokens x (x,y,z,pad)
    __shared__ float s_red[4];
    __shared__ unsigned s_redc[4];

    int tid  = threadIdx.x;
    int wid  = tid >> 5;
    int lane = tid & 31;
    int g    = lane >> 2;       // group row (0..7)
    int tig  = lane & 3;        // thread in group (0..3)
    int r0 = blockIdx.x * TOK;  // first token row (b*N + i); N % TOK == 0
    int b  = r0 / N;

    for (int idx = tid; idx < NB_PAD * 32; idx += 128) {
        int row = idx >> 5, cp = idx & 31;
        float f0 = 0.0f, f1 = 0.0f;
        if (row < NUM_BINS) {
            f0 = wb_w[row * D_LOW + cp * 2];
            f1 = wb_w[row * D_LOW + cp * 2 + 1];
        }
        uint32_t v; CVT_BF2(v, f0, f1);
        s_Wb[idx] = v;
    }
    if (tid < TOK * 32) {
        int tok = tid >> 5, w = tid & 31;
        float f0 = g_U[(size_t)(r0 + tok) * D_LOW + w * 2];
        float f1 = g_U[(size_t)(r0 + tok) * D_LOW + w * 2 + 1];
        uint32_t v; CVT_BF2(v, f0, f1);
        s_U[tid] = v;
    }
    if (tid < NB_PAD) s_wbb[tid] = (tid < NUM_BINS) ? wb_b[tid] : 0.0f;
    if (tid < TOK) {
        size_t xb = (size_t)(r0 + tid) * 3;
        s_xi[tid * 4 + 0] = x_true[xb];
        s_xi[tid * 4 + 1] = x_true[xb + 1];
        s_xi[tid * 4 + 2] = x_true[xb + 2];
        s_xi[tid * 4 + 3] = pad[r0 + tid];
    }
    __syncthreads();

    // B fragments (constant across all chunks and tokens)
    uint32_t breg[40];
    #pragma unroll
    for (int ks = 0; ks < 4; ks++) {
        #pragma unroll
        for (int nt = 0; nt < 5; nt++) {
            int row = nt * 8 + g;
            int cp  = ks * 8 + tig;
            breg[ks * 10 + nt * 2 + 0] = s_Wb[row * 32 + cp];
            breg[ks * 10 + nt * 2 + 1] = s_Wb[row * 32 + cp + 4];
        }
    }
    // bias for this lane's D columns
    float bias0[5], bias1[5];
    #pragma unroll
    for (int nt = 0; nt < 5; nt++) {
        bias0[nt] = s_wbb[nt * 8 + 2 * tig];
        bias1[nt] = s_wbb[nt * 8 + 2 * tig + 1];
    }

    float* sDw = s_D[wid];
    const uint32_t* sv32 = reinterpret_cast<const uint32_t*>(s_V);

    float cv = 0.0f; unsigned cc = 0u;
    int nchunks = (N + JT - 1) / JT;

    for (int jc = 0; jc < nchunks; jc++) {
        __syncwarp();
        int jw = jc * JT + wid * 32;      // this warp's first j

        // stage V rows jw..jw+31 (coalesced: 8 lanes per 128B row)
        {
            const uint4* src = reinterpret_cast<const uint4*>(g_Vb) + ((size_t)b * N) * 8;
            #pragma unroll
            for (int it = 0; it < 8; it++) {
                int idx = it * 32 + lane;
                int row = idx >> 3, q = idx & 7;
                int j = jw + row;
                uint4 v = make_uint4(0u, 0u, 0u, 0u);
                if (j < N) v = src[(size_t)j * 8 + q];
                s_V[(wid * 32 + row) * 9 + q] = v;
            }
        }

        // j-coordinates loaded once, reused by all tokens
        int j = jw + lane;
        float xj0 = 0.f, xj1 = 0.f, xj2 = 0.f, pj = 0.f;
        if (j < N) {
            size_t xb = ((size_t)b * N + j) * 3;
            xj0 = x_true[xb]; xj1 = x_true[xb + 1]; xj2 = x_true[xb + 2];
            pj = pad[(size_t)b * N + j];
        }
        __syncwarp();

        #pragma unroll
        for (int tok = 0; tok < TOK; tok++) {
            // U words for this token (from smem; keeps register count flat)
            uint32_t ureg[8];
            #pragma unroll
            for (int ks = 0; ks < 4; ks++) {
                ureg[2 * ks + 0] = s_U[tok * 32 + ks * 8 + tig];
                ureg[2 * ks + 1] = s_U[tok * 32 + ks * 8 + tig + 4];
            }

            // acc init = bias (folds wb_b into the GEMM)
            float acc[2][5][4];
            #pragma unroll
            for (int m = 0; m < 2; m++)
                #pragma unroll
                for (int nt = 0; nt < 5; nt++) {
                    acc[m][nt][0] = bias0[nt];
                    acc[m][nt][1] = bias1[nt];
                    acc[m][nt][2] = bias0[nt];
                    acc[m][nt][3] = bias1[nt];
                }

            // A-fragments: V word (conflict-free LDS.32) * U word
            #pragma unroll
            for (int m = 0; m < 2; m++) {
                int row0 = wid * 32 + m * 16 + g;
                #pragma unroll
                for (int ks = 0; ks < 4; ks++) {
                    int w0 = row0 * VW + ks * 8 + tig;
                    uint32_t a0 = sv32[w0];
                    uint32_t a1 = sv32[w0 + 8 * VW];
                    uint32_t a2 = sv32[w0 + 4];
                    uint32_t a3 = sv32[w0 + 8 * VW + 4];
                    MULBF2(a0, a0, ureg[2 * ks]);
                    MULBF2(a1, a1, ureg[2 * ks]);
                    MULBF2(a2, a2, ureg[2 * ks + 1]);
                    MULBF2(a3, a3, ureg[2 * ks + 1]);
                    #pragma unroll
                    for (int nt = 0; nt < 5; nt++)
                        MMA_BF16(acc[m][nt], a0, a1, a2, a3,
                                 breg[ks * 10 + nt * 2], breg[ks * 10 + nt * 2 + 1]);
                }
            }
            __syncwarp();

            // D -> smem (pair-major, 41-float stride)
            #pragma unroll
            for (int m = 0; m < 2; m++) {
                int p0 = m * 16 + g;
                #pragma unroll
                for (int nt = 0; nt < 5; nt++) {
                    int col = nt * 8 + tig * 2;
                    sDw[p0 * DSTRIDE + col]           = acc[m][nt][0];
                    sDw[p0 * DSTRIDE + col + 1]       = acc[m][nt][1];
                    sDw[(p0 + 8) * DSTRIDE + col]     = acc[m][nt][2];
                    sDw[(p0 + 8) * DSTRIDE + col + 1] = acc[m][nt][3];
                }
            }
            __syncwarp();

            // epilogue: pair = lane, single-pass maxless logsumexp
            const float* lrow = sDw + lane * DSTRIDE;
            float xi0 = s_xi[tok * 4 + 0];
            float xi1 = s_xi[tok * 4 + 1];
            float xi2 = s_xi[tok * 4 + 2];
            float pi  = s_xi[tok * 4 + 3];
            float dx = xi0 - xj0, dy = xi1 - xj1, dz = xi2 - xj2;
            float dist = sqrtf(dx * dx + dy * dy + dz * dz);
            int bin = (int)((dist - DIST_MIN_F) / BIN_W);
            bin = min(max(bin, 0), NUM_BINS - 1);

            float ssum = 0.0f, tl = 0.0f;
            #pragma unroll
            for (int k = 0; k < NUM_BINS; k++) {
                float lv = lrow[k];
                ssum += __expf(lv);
                if (k == bin) tl = lv;
            }
            float ce = __logf(ssum) - tl;

            bool ok = (j < N) && (pi * pj > 0.0f);
            cv += ok ? ce : 0.0f;
            cc += ok ? 1u : 0u;
            __syncwarp();
        }
    }

    #pragma unroll
    for (int o = 16; o > 0; o >>= 1) {
        cv += __shfl_down_sync(0xffffffffu, cv, o);
        cc += __shfl_down_sync(0xffffffffu, cc, o);
    }
    if (lane == 0) { s_red[wid] = cv; s_redc[wid] = cc; }
    __syncthreads();
    if (tid == 0) {
        float S = s_red[0] + s_red[1] + s_red[2] + s_red[3];
        unsigned C = s_redc[0] + s_redc[1] + s_redc[2] + s_redc[3];
        atomicAdd(&g_ce[b], (double)S);
        atomicAdd(&g_cnt[b], C);
        __threadfence();
        unsigned done = atomicAdd(&g_done, 1u);
        if (done == (unsigned)(total_ctas - 1)) {
            __threadfence();
            double loss = 0.0;
            int valid = 0;
            for (int bb = 0; bb < B; bb++) {
                if (g_cnt[bb] > 0u) { loss += g_ce[bb] / (double)g_cnt[bb]; valid++; }
            }
            out[0] = (float)(valid > 0 ? loss / (double)valid : 0.0);
        }
    }
}

// ---------------------------------------------------------------------------
extern "C" void kernel_launch(void* const* d_in, const int* in_sizes, int n_in,
                              void* d_out, int out_size)
{
    const float* h_res  = (const float*)d_in[0];
    const float* x_true = (const float*)d_in[1];
    const float* padm   = (const float*)d_in[2];
    const float* ln_w   = (const float*)d_in[3];
    const float* ln_b   = (const float*)d_in[4];
    const float* wu_w   = (const float*)d_in[5];
    const float* wu_b   = (const float*)d_in[6];
    const float* wv_w   = (const float*)d_in[7];
    const float* wv_b   = (const float*)d_in[8];
    const float* wb_w   = (const float*)d_in[9];
    const float* wb_b   = (const float*)d_in[10];

    int BN = in_sizes[0] / D_MODEL;   // B*N
    int B = 2;
    int N = BN / B;

    dim3 tgrid(4, 16);
    transpose_kernel<<<tgrid, 256>>>(wu_w, wv_w);

    prep_kernel<<<(BN / TR) * 2, 256>>>(h_res, ln_w, ln_b, wu_b, wv_b);

    main_kernel<<<BN / TOK, 128>>>(x_true, padm, wb_w, wb_b, B, N, (float*)d_out, BN / TOK);
}

// round 13
// speedup vs baseline: 1.3765x; 1.0894x over previous
#include <cuda_runtime.h>
#include <cuda_bf16.h>
#include <math.h>
#include <stdint.h>

#define D_MODEL 512
#define D_LOW   64
#define NUM_BINS 39
#define NB_PAD  40
#define DIST_MIN_F 2.0f
#define DIST_MAX_F 22.0f
#define BIN_W  ((DIST_MAX_F - DIST_MIN_F) / (float)(NUM_BINS - 1))
#define LN_EPS 1e-5f
#define MAX_ROWS 4096
#define JT 128
#define TOK 4                  // tokens per CTA (main)
#define TR 16                  // rows per CTA (prep)
#define CHK 128                // channel chunk (prep weight tile)

__device__ float g_U[MAX_ROWS * D_LOW];
__device__ unsigned long long g_Vb[MAX_ROWS * (D_LOW / 4)];  // 4 bf16 per u64
__device__ double g_ce[8];
__device__ unsigned int g_cnt[8];
__device__ unsigned int g_done;

__device__ __forceinline__ uint32_t smem_u32(const void* p) {
    uint32_t a;
    asm("{ .reg .u64 t; cvta.to.shared.u64 t, %1; cvt.u32.u64 %0, t; }" : "=r"(a) : "l"(p));
    return a;
}
#define CVT_BF2(res, lo, hi) \
    asm("cvt.rn.satfinite.bf16x2.f32 %0, %1, %2;" : "=r"(res) : "f"(hi), "f"(lo))
#define MULBF2(res, a, b) \
    asm("mul.bf16x2 %0, %1, %2;" : "=r"(res) : "r"(a), "r"(b))

#define MMA_BF16(d, a0, a1, a2, a3, b0, b1) \
    asm volatile("mma.sync.aligned.m16n8k16.row.col.f32.bf16.bf16.f32 " \
                 "{%0,%1,%2,%3}, {%4,%5,%6,%7}, {%8,%9}, {%0,%1,%2,%3};" \
                 : "+f"((d)[0]), "+f"((d)[1]), "+f"((d)[2]), "+f"((d)[3]) \
                 : "r"(a0), "r"(a1), "r"(a2), "r"(a3), "r"(b0), "r"(b1))

// ---------------------------------------------------------------------------
// Kernel 1: LayerNorm + projections with in-kernel weight transpose.
// grid = (BN/16)*2; bid = rowblock*2 + half (half 0 -> U, half 1 -> V bf16).
// Weight chunk loaded coalesced from the original [o][c] layout into
// smem transposed Ws[c][o] (stride-68 rows -> conflict-free LDS.128).
// Dynamic smem: sh[16*512] + Ws[CHK*68].
// ---------------------------------------------------------------------------
extern __shared__ float prep_dsm[];

__global__ void __launch_bounds__(256) prep_kernel(
    const float* __restrict__ h_res,
    const float* __restrict__ ln_w, const float* __restrict__ ln_b,
    const float* __restrict__ wu_w, const float* __restrict__ wu_b,
    const float* __restrict__ wv_w, const float* __restrict__ wv_b)
{
    float* sh = prep_dsm;                 // 16*512 floats
    float* Ws = prep_dsm + TR * D_MODEL;  // CHK*68 floats

    int t    = threadIdx.x;
    int warp = t >> 5;
    int lane = t & 31;
    int rb   = blockIdx.x >> 1;
    int half = blockIdx.x & 1;

    // zero global accumulators (runs before main_kernel, stream-ordered)
    if (blockIdx.x == 0) {
        if (t < 8) { g_ce[t] = 0.0; g_cnt[t] = 0u; }
        if (t == 8) g_done = 0u;
    }

    // ---- LayerNorm: warp = 2 rows ----
    #pragma unroll
    for (int rr = 0; rr < 2; rr++) {
        int lr  = warp * 2 + rr;
        size_t row = (size_t)rb * TR + lr;
        const float4* hp = reinterpret_cast<const float4*>(h_res) + row * (D_MODEL / 4);
        float4 a[4];
        #pragma unroll
        for (int q = 0; q < 4; q++) a[q] = hp[lane + 32 * q];
        float s = 0.0f, sq = 0.0f;
        #pragma unroll
        for (int q = 0; q < 4; q++) {
            s  += a[q].x + a[q].y + a[q].z + a[q].w;
            sq += a[q].x*a[q].x + a[q].y*a[q].y + a[q].z*a[q].z + a[q].w*a[q].w;
        }
        #pragma unroll
        for (int o = 16; o > 0; o >>= 1) {
            s  += __shfl_xor_sync(0xffffffffu, s,  o);
            sq += __shfl_xor_sync(0xffffffffu, sq, o);
        }
        float mu   = s * (1.0f / (float)D_MODEL);
        float var  = sq * (1.0f / (float)D_MODEL) - mu * mu;
        float istd = rsqrtf(var + LN_EPS);

        const float4* wp = reinterpret_cast<const float4*>(ln_w);
        const float4* bp = reinterpret_cast<const float4*>(ln_b);
        float4* shp = reinterpret_cast<float4*>(sh) + lr * (D_MODEL / 4);
        #pragma unroll
        for (int q = 0; q < 4; q++) {
            float4 w4 = wp[lane + 32 * q];
            float4 b4 = bp[lane + 32 * q];
            float4 nv;
            nv.x = (a[q].x - mu) * istd * w4.x + b4.x;
            nv.y = (a[q].y - mu) * istd * w4.y + b4.y;
            nv.z = (a[q].z - mu) * istd * w4.z + b4.z;
            nv.w = (a[q].w - mu) * istd * w4.w + b4.w;
            shp[lane + 32 * q] = nv;
        }
    }
    __syncthreads();

    // ---- GEMM over 4 channel chunks; weights transposed through smem ----
    const float* wsrc = (half == 0) ? wu_w : wv_w;
    int ty = t >> 4;            // 0..15 row
    int tx = t & 15;            // 0..15 col group (local col = tx*4)

    float a0 = 0.0f, a1 = 0.0f, a2 = 0.0f, a3 = 0.0f;

    for (int cc = 0; cc < D_MODEL; cc += CHK) {
        // load W chunk [64 out][CHK ch], coalesced LDG, transposed STS
        #pragma unroll
        for (int it = 0; it < (D_LOW * CHK) / 256; it++) {
            int idx = t + it * 256;
            int c = idx & (CHK - 1);
            int o = idx >> 7;
            Ws[c * 68 + o] = wsrc[(size_t)o * D_MODEL + cc + c];
        }
        __syncthreads();

        const float* shr = sh + ty * D_MODEL + cc;
        #pragma unroll 4
        for (int c = 0; c < CHK; c++) {
            float4 w = *reinterpret_cast<const float4*>(Ws + c * 68 + tx * 4);
            float h = shr[c];
            a0 = fmaf(h, w.x, a0);
            a1 = fmaf(h, w.y, a1);
            a2 = fmaf(h, w.z, a2);
            a3 = fmaf(h, w.w, a3);
        }
        __syncthreads();
    }

    size_t grow = (size_t)rb * TR + ty;
    int lcol = tx * 4;
    if (half == 0) {
        float4 b = *reinterpret_cast<const float4*>(wu_b + lcol);
        *reinterpret_cast<float4*>(g_U + grow * D_LOW + lcol) =
            make_float4(a0 + b.x, a1 + b.y, a2 + b.z, a3 + b.w);
    } else {
        float4 b = *reinterpret_cast<const float4*>(wv_b + lcol);
        float v0 = a0 + b.x, v1 = a1 + b.y, v2 = a2 + b.z, v3 = a3 + b.w;
        uint32_t lo, hi;
        CVT_BF2(lo, v0, v1); CVT_BF2(hi, v2, v3);
        g_Vb[grow * 16 + (lcol >> 2)] = (unsigned long long)lo | ((unsigned long long)hi << 32);
    }
}

// ---------------------------------------------------------------------------
// Kernel 2: mma.sync bilinear, FOUR tokens per CTA sharing each staged V
// chunk (byte-identical to R12 / 82.7us path). Last CTA finalizes scalar.
// ---------------------------------------------------------------------------
#define DSTRIDE 41            // floats per D row (odd -> conflict-free scalar LDS)
#define VW 36                 // words per s_V row (9 uint4)

__global__ void __launch_bounds__(128) main_kernel(
    const float* __restrict__ x_true, const float* __restrict__ pad,
    const float* __restrict__ wb_w,  const float* __restrict__ wb_b,
    int B, int N, float* __restrict__ out, int total_ctas)
{
    __shared__ uint4 s_V[JT * 9];                 // 18432 B
    __shared__ float s_D[4][32 * DSTRIDE];        // 20992 B
    __shared__ uint32_t s_Wb[NB_PAD * 32];        // 5120 B
    __shared__ uint32_t s_U[TOK * 32];            // 4 tokens x 32 bf16x2
    __shared__ float s_wbb[NB_PAD];
    __shared__ float s_xi[TOK * 4];               // 4 tokens x (x,y,z,pad)
    __shared__ float s_red[4];
    __shared__ unsigned s_redc[4];

    int tid  = threadIdx.x;
    int wid  = tid >> 5;
    int lane = tid & 31;
    int g    = lane >> 2;       // group row (0..7)
    int tig  = lane & 3;        // thread in group (0..3)
    int r0 = blockIdx.x * TOK;  // first token row (b*N + i); N % TOK == 0
    int b  = r0 / N;

    for (int idx = tid; idx < NB_PAD * 32; idx += 128) {
        int row = idx >> 5, cp = idx & 31;
        float f0 = 0.0f, f1 = 0.0f;
        if (row < NUM_BINS) {
            f0 = wb_w[row * D_LOW + cp * 2];
            f1 = wb_w[row * D_LOW + cp * 2 + 1];
        }
        uint32_t v; CVT_BF2(v, f0, f1);
        s_Wb[idx] = v;
    }
    if (tid < TOK * 32) {
        int tok = tid >> 5, w = tid & 31;
        float f0 = g_U[(size_t)(r0 + tok) * D_LOW + w * 2];
        float f1 = g_U[(size_t)(r0 + tok) * D_LOW + w * 2 + 1];
        uint32_t v; CVT_BF2(v, f0, f1);
        s_U[tid] = v;
    }
    if (tid < NB_PAD) s_wbb[tid] = (tid < NUM_BINS) ? wb_b[tid] : 0.0f;
    if (tid < TOK) {
        size_t xb = (size_t)(r0 + tid) * 3;
        s_xi[tid * 4 + 0] = x_true[xb];
        s_xi[tid * 4 + 1] = x_true[xb + 1];
        s_xi[tid * 4 + 2] = x_true[xb + 2];
        s_xi[tid * 4 + 3] = pad[r0 + tid];
    }
    __syncthreads();

    // B fragments (constant across all chunks and tokens)
    uint32_t breg[40];
    #pragma unroll
    for (int ks = 0; ks < 4; ks++) {
        #pragma unroll
        for (int nt = 0; nt < 5; nt++) {
            int row = nt * 8 + g;
            int cp  = ks * 8 + tig;
            breg[ks * 10 + nt * 2 + 0] = s_Wb[row * 32 + cp];
            breg[ks * 10 + nt * 2 + 1] = s_Wb[row * 32 + cp + 4];
        }
    }
    // bias for this lane's D columns
    float bias0[5], bias1[5];
    #pragma unroll
    for (int nt = 0; nt < 5; nt++) {
        bias0[nt] = s_wbb[nt * 8 + 2 * tig];
        bias1[nt] = s_wbb[nt * 8 + 2 * tig + 1];
    }

    float* sDw = s_D[wid];
    const uint32_t* sv32 = reinterpret_cast<const uint32_t*>(s_V);

    float cv = 0.0f; unsigned cc = 0u;
    int nchunks = (N + JT - 1) / JT;

    for (int jc = 0; jc < nchunks; jc++) {
        __syncwarp();
        int jw = jc * JT + wid * 32;      // this warp's first j

        // stage V rows jw..jw+31 (coalesced: 8 lanes per 128B row)
        {
            const uint4* src = reinterpret_cast<const uint4*>(g_Vb) + ((size_t)b * N) * 8;
            #pragma unroll
            for (int it = 0; it < 8; it++) {
                int idx = it * 32 + lane;
                int row = idx >> 3, q = idx & 7;
                int j = jw + row;
                uint4 v = make_uint4(0u, 0u, 0u, 0u);
                if (j < N) v = src[(size_t)j * 8 + q];
                s_V[(wid * 32 + row) * 9 + q] = v;
            }
        }

        // j-coordinates loaded once, reused by all tokens
        int j = jw + lane;
        float xj0 = 0.f, xj1 = 0.f, xj2 = 0.f, pj = 0.f;
        if (j < N) {
            size_t xb = ((size_t)b * N + j) * 3;
            xj0 = x_true[xb]; xj1 = x_true[xb + 1]; xj2 = x_true[xb + 2];
            pj = pad[(size_t)b * N + j];
        }
        __syncwarp();

        #pragma unroll
        for (int tok = 0; tok < TOK; tok++) {
            // U words for this token (from smem; keeps register count flat)
            uint32_t ureg[8];
            #pragma unroll
            for (int ks = 0; ks < 4; ks++) {
                ureg[2 * ks + 0] = s_U[tok * 32 + ks * 8 + tig];
                ureg[2 * ks + 1] = s_U[tok * 32 + ks * 8 + tig + 4];
            }

            // acc init = bias (folds wb_b into the GEMM)
            float acc[2][5][4];
            #pragma unroll
            for (int m = 0; m < 2; m++)
                #pragma unroll
                for (int nt = 0; nt < 5; nt++) {
                    acc[m][nt][0] = bias0[nt];
                    acc[m][nt][1] = bias1[nt];
                    acc[m][nt][2] = bias0[nt];
                    acc[m][nt][3] = bias1[nt];
                }

            // A-fragments: V word (conflict-free LDS.32) * U word
            #pragma unroll
            for (int m = 0; m < 2; m++) {
                int row0 = wid * 32 + m * 16 + g;
                #pragma unroll
                for (int ks = 0; ks < 4; ks++) {
                    int w0 = row0 * VW + ks * 8 + tig;
                    uint32_t a0 = sv32[w0];
                    uint32_t a1 = sv32[w0 + 8 * VW];
                    uint32_t a2 = sv32[w0 + 4];
                    uint32_t a3 = sv32[w0 + 8 * VW + 4];
                    MULBF2(a0, a0, ureg[2 * ks]);
                    MULBF2(a1, a1, ureg[2 * ks]);
                    MULBF2(a2, a2, ureg[2 * ks + 1]);
                    MULBF2(a3, a3, ureg[2 * ks + 1]);
                    #pragma unroll
                    for (int nt = 0; nt < 5; nt++)
                        MMA_BF16(acc[m][nt], a0, a1, a2, a3,
                                 breg[ks * 10 + nt * 2], breg[ks * 10 + nt * 2 + 1]);
                }
            }
            __syncwarp();

            // D -> smem (pair-major, 41-float stride)
            #pragma unroll
            for (int m = 0; m < 2; m++) {
                int p0 = m * 16 + g;
                #pragma unroll
                for (int nt = 0; nt < 5; nt++) {
                    int col = nt * 8 + tig * 2;
                    sDw[p0 * DSTRIDE + col]           = acc[m][nt][0];
                    sDw[p0 * DSTRIDE + col + 1]       = acc[m][nt][1];
                    sDw[(p0 + 8) * DSTRIDE + col]     = acc[m][nt][2];
                    sDw[(p0 + 8) * DSTRIDE + col + 1] = acc[m][nt][3];
                }
            }
            __syncwarp();

            // epilogue: pair = lane, single-pass maxless logsumexp
            const float* lrow = sDw + lane * DSTRIDE;
            float xi0 = s_xi[tok * 4 + 0];
            float xi1 = s_xi[tok * 4 + 1];
            float xi2 = s_xi[tok * 4 + 2];
            float pi  = s_xi[tok * 4 + 3];
            float dx = xi0 - xj0, dy = xi1 - xj1, dz = xi2 - xj2;
            float dist = sqrtf(dx * dx + dy * dy + dz * dz);
            int bin = (int)((dist - DIST_MIN_F) / BIN_W);
            bin = min(max(bin, 0), NUM_BINS - 1);

            float ssum = 0.0f, tl = 0.0f;
            #pragma unroll
            for (int k = 0; k < NUM_BINS; k++) {
                float lv = lrow[k];
                ssum += __expf(lv);
                if (k == bin) tl = lv;
            }
            float ce = __logf(ssum) - tl;

            bool ok = (j < N) && (pi * pj > 0.0f);
            cv += ok ? ce : 0.0f;
            cc += ok ? 1u : 0u;
            __syncwarp();
        }
    }

    #pragma unroll
    for (int o = 16; o > 0; o >>= 1) {
        cv += __shfl_down_sync(0xffffffffu, cv, o);
        cc += __shfl_down_sync(0xffffffffu, cc, o);
    }
    if (lane == 0) { s_red[wid] = cv; s_redc[wid] = cc; }
    __syncthreads();
    if (tid == 0) {
        float S = s_red[0] + s_red[1] + s_red[2] + s_red[3];
        unsigned C = s_redc[0] + s_redc[1] + s_redc[2] + s_redc[3];
        atomicAdd(&g_ce[b], (double)S);
        atomicAdd(&g_cnt[b], C);
        __threadfence();
        unsigned done = atomicAdd(&g_done, 1u);
        if (done == (unsigned)(total_ctas - 1)) {
            __threadfence();
            double loss = 0.0;
            int valid = 0;
            for (int bb = 0; bb < B; bb++) {
                if (g_cnt[bb] > 0u) { loss += g_ce[bb] / (double)g_cnt[bb]; valid++; }
            }
            out[0] = (float)(valid > 0 ? loss / (double)valid : 0.0);
        }
    }
}

// ---------------------------------------------------------------------------
extern "C" void kernel_launch(void* const* d_in, const int* in_sizes, int n_in,
                              void* d_out, int out_size)
{
    const float* h_res  = (const float*)d_in[0];
    const float* x_true = (const float*)d_in[1];
    const float* padm   = (const float*)d_in[2];
    const float* ln_w   = (const float*)d_in[3];
    const float* ln_b   = (const float*)d_in[4];
    const float* wu_w   = (const float*)d_in[5];
    const float* wu_b   = (const float*)d_in[6];
    const float* wv_w   = (const float*)d_in[7];
    const float* wv_b   = (const float*)d_in[8];
    const float* wb_w   = (const float*)d_in[9];
    const float* wb_b   = (const float*)d_in[10];

    int BN = in_sizes[0] / D_MODEL;   // B*N
    int B = 2;
    int N = BN / B;

    const int prep_smem = (TR * D_MODEL + CHK * 68) * (int)sizeof(float);  // ~67.6 KB
    cudaFuncSetAttribute(prep_kernel, cudaFuncAttributeMaxDynamicSharedMemorySize, prep_smem);

    prep_kernel<<<(BN / TR) * 2, 256, prep_smem>>>(h_res, ln_w, ln_b,
                                                   wu_w, wu_b, wv_w, wv_b);

    main_kernel<<<BN / TOK, 128>>>(x_true, padm, wb_w, wb_b, B, N, (float*)d_out, BN / TOK);
}